// round 17
// baseline (speedup 1.0000x reference)
#include <cuda_runtime.h>
#include <stdint.h>

// ---------------------------------------------------------------------------
// Problem constants (DSEC 480x640, 4x4 voxels, B=4)
// ---------------------------------------------------------------------------
#define NV0 120
#define NV1 160
#define NBATCH 4
#define KC (NBATCH * NV0 * NV1)   /* 76800 */
#define DIM 64

#define N_MAX (1 << 20)
#define E_MAX (1 << 23)
#define NB (1 << 20)              /* scan array size */
#define NBE 720896                /* max used bucket bound (covers is64) */
#define NBLK (NB / 1024)
#define SH 13                     /* bucket shift, both paths */
#define LOWMASK 0x1FFFu
#define CAP 48                    /* slab capacity per bucket */
#define OCAP 8192
#define MBUF 128

// int32-wrapped sentinel: (int32)(76800*76800) = 1603272704
#define SENT32 1603272704
#define SENT64 5898240000ull
#define USENT32 3750756352u
#define SENTB32 (USENT32 >> SH)        /* 457856 (exact, low bits 0) */
#define SENTB64 ((unsigned)(SENT64 >> SH))  /* 720000 (exact) */

// Output layout (float32 flatten, reference return order):
#define OFF_POS   (KC * DIM)
#define OFF_BATCH (OFF_POS + KC * 3)
#define OFF_MASK  (OFF_BATCH + KC)
#define OFF_EI    (OFF_MASK + KC)

// ---------------------------------------------------------------------------
// Static device scratch
// ---------------------------------------------------------------------------
__device__ int            g_is64;
__device__ unsigned int   g_sent;
__device__ unsigned int   g_ocnt;
__device__ int            g_cluster[N_MAX];
__device__ unsigned int   g_counts[KC];
__device__ float          g_possum[KC * 3];
__device__ unsigned int   g_nodelist[N_MAX];
__device__ unsigned int   g_koff[KC];
__device__ unsigned int   g_kcur[KC];
__device__ unsigned short g_slab[(size_t)NBE * CAP];
__device__ unsigned long long g_oflow[OCAP];
__device__ unsigned int   g_bcnt[NB];
__device__ unsigned int   g_incl[NB];
__device__ unsigned int   g_bsum[NBLK];

__device__ __forceinline__ int ld_id(const void* p, long long i, int is64) {
    return is64 ? (int)((const long long*)p)[i] : ((const int*)p)[i];
}
__device__ __forceinline__ int clampi(int v, int lo, int hi) {
    return v < lo ? lo : (v > hi ? hi : v);
}

__device__ __forceinline__ unsigned int edge_k32(int sc, int dc) {
    int key32 = (sc == dc) ? SENT32
              : (int)((unsigned int)sc * 76800u + (unsigned int)dc);
    return ((unsigned int)key32) ^ 0x80000000u;
}
__device__ __forceinline__ unsigned long long edge_uk64(int sc, int dc) {
    if (sc == dc) return SENT64;
    return (unsigned long long)(unsigned int)sc * 76800ull
         + (unsigned long long)(unsigned int)dc;
}

// full decode (rare path only)
__device__ __forceinline__ void decode_key(unsigned long long uk, int is64,
                                           float* sf, float* df, bool* valid) {
    if (is64) {
        *valid = (uk < SENT64);
        *sf = (float)(long long)(uk / 76800ull);
        *df = (float)(long long)(uk % 76800ull);
    } else {
        unsigned int u = (unsigned int)uk;
        *valid = (u < USENT32);
        unsigned int q = __umulhi(u >> 10, 57266231u);
        unsigned int r = u - q * 76800u;
        int qf; unsigned int rf;
        if (r >= 2048u) { qf = (int)q - 27962; rf = r - 2048u; }
        else            { qf = (int)q - 27963; rf = r + 74752u; }
        *sf = (float)qf;
        *df = (float)rf;
    }
}

__device__ __forceinline__ void emit_pos(float* __restrict__ out, int E,
                                         unsigned int bucket,
                                         int is64, unsigned int v,
                                         bool first, long long p) {
    const long long off_ei = OFF_EI;
    const long long off_em = off_ei + 2ll * E;
    unsigned long long uk = (((unsigned long long)bucket) << SH) | v;
    float sf, df; bool valid;
    decode_key(uk, is64, &sf, &df, &valid);
    bool mask = first && valid;
    out[off_ei + p]     = mask ? sf   : -1.0f;
    out[off_ei + E + p] = mask ? df   : -1.0f;
    out[off_em + p]     = mask ? 1.0f : 0.0f;
}

// ---------------------------------------------------------------------------
__global__ void init_kernel(const unsigned int* ew) {
    int i = blockIdx.x * blockDim.x + threadIdx.x;
    if (i == 0) {
        unsigned int o = 0;
        for (int k = 1; k < 128; k += 2) o |= ew[k];
        g_is64 = (o == 0u) ? 1 : 0;
        g_sent = 0u;
        g_ocnt = 0u;
    }
    if (i >= NB / 4) return;
    ((uint4*)g_bcnt)[i] = make_uint4(0u, 0u, 0u, 0u);
    if (i < KC / 4)     ((uint4*)g_counts)[i] = make_uint4(0u, 0u, 0u, 0u);
    if (i < KC * 3 / 4) ((uint4*)g_possum)[i] = make_uint4(0u, 0u, 0u, 0u);
}

__global__ void cluster_kernel(const float* __restrict__ pos,
                               const void* batch, int N) {
    int i = blockIdx.x * blockDim.x + threadIdx.x;
    if (i >= N) return;
    int is64 = g_is64;
    float p0 = pos[3 * i + 0];
    float p1 = pos[3 * i + 1];
    float p2 = pos[3 * i + 2];
    int c0 = clampi((int)floorf(p1 * 0.25f), 0, NV0 - 1);
    int c1 = clampi((int)floorf(p2 * 0.25f), 0, NV1 - 1);
    int b  = clampi(ld_id(batch, i, is64), 0, NBATCH - 1);
    int c  = c0 + c1 * NV0 + b * (NV0 * NV1);
    g_cluster[i] = c;
    atomicAdd(&g_counts[c], 1u);
    atomicAdd(&g_possum[3 * c + 0], p0);
    atomicAdd(&g_possum[3 * c + 1], p1);
    atomicAdd(&g_possum[3 * c + 2], p2);
}

// node-chain: exclusive scan of cluster counts (one block)
__global__ void nodescan_kernel() {
    __shared__ unsigned int sums[1024];
    const int PER = KC / 1024;
    int t = threadIdx.x;
    unsigned int s = 0;
    #pragma unroll 5
    for (int i = 0; i < PER; i++) s += g_counts[t * PER + i];
    sums[t] = s;
    __syncthreads();
    for (int d = 1; d < 1024; d <<= 1) {
        unsigned int v = (t >= d) ? sums[t - d] : 0u;
        __syncthreads();
        sums[t] += v;
        __syncthreads();
    }
    unsigned int prefix = (t == 0) ? 0u : sums[t - 1];
    for (int i = 0; i < PER; i++) {
        g_koff[t * PER + i] = prefix;
        g_kcur[t * PER + i] = prefix;
        prefix += g_counts[t * PER + i];
    }
}

__global__ void nodescatter_kernel(int N) {
    int i = blockIdx.x * blockDim.x + threadIdx.x;
    if (i >= N) return;
    int c = g_cluster[i];
    unsigned int pos = atomicAdd(&g_kcur[c], 1u);
    if (pos < (unsigned int)N) g_nodelist[pos] = (unsigned int)i;
}

__global__ void xmax2_kernel(const float* __restrict__ x,
                             float* __restrict__ out, int N) {
    int c    = (blockIdx.x * blockDim.x + threadIdx.x) >> 5;
    int lane = threadIdx.x & 31;
    if (c >= KC) return;
    unsigned int n     = g_counts[c];
    unsigned int start = g_koff[c];
    float2 acc = make_float2(-__int_as_float(0x7F800000), -__int_as_float(0x7F800000));
    for (unsigned int m = 0; m < n; m++) {
        unsigned int nid = g_nodelist[start + m];
        float2 v = ((const float2*)(x + (size_t)nid * DIM))[lane];
        acc.x = fmaxf(acc.x, v.x);
        acc.y = fmaxf(acc.y, v.y);
    }
    if (n == 0) acc = make_float2(0.0f, 0.0f);
    ((float2*)out)[(size_t)c * 32 + lane] = acc;
}

__global__ void finalize_kernel(float* __restrict__ out) {
    int i = blockIdx.x * blockDim.x + threadIdx.x;
    if (i >= KC * 3) return;
    {
        int c = i / 3;
        unsigned int cnt = g_counts[c];
        out[OFF_POS + i] = g_possum[i] / (float)(cnt > 0u ? cnt : 1u);
    }
    if (i < KC) {
        out[OFF_BATCH + i] = (float)(i / (NV0 * NV1));
        out[OFF_MASK + i]  = (g_counts[i] > 0u) ? 1.0f : 0.0f;
    }
}

// ---------------------------------------------------------------------------
// FUSED edge pass: 8 edges per thread
// ---------------------------------------------------------------------------
__device__ __forceinline__ void place32(unsigned int k) {
    if (k == USENT32) {
        atomicAdd(&g_sent, 1u);
    } else {
        unsigned int b = k >> SH;
        unsigned int pos = atomicAdd(&g_bcnt[b], 1u);
        if (pos < CAP) {
            g_slab[(size_t)b * CAP + pos] = (unsigned short)(k & LOWMASK);
        } else {
            unsigned int o = atomicAdd(&g_ocnt, 1u);
            if (o < OCAP) g_oflow[o] = (unsigned long long)k;
        }
    }
}

__global__ void edge_fused_kernel(const void* eidx, int N, int E) {
    int t = blockIdx.x * blockDim.x + threadIdx.x;
    int is64 = g_is64;
    if (!is64) {
        if ((E & 7) == 0) {
            int no = E >> 3;
            if (t >= no) return;
            const int4* r0 = (const int4*)eidx;
            const int4* r1 = (const int4*)((const int*)eidx + E);
            int4 ua = r0[2 * t],     ub = r0[2 * t + 1];
            int4 va = r1[2 * t],     vb = r1[2 * t + 1];
            int s0 = g_cluster[clampi(ua.x, 0, N - 1)];
            int s1 = g_cluster[clampi(ua.y, 0, N - 1)];
            int s2 = g_cluster[clampi(ua.z, 0, N - 1)];
            int s3 = g_cluster[clampi(ua.w, 0, N - 1)];
            int s4 = g_cluster[clampi(ub.x, 0, N - 1)];
            int s5 = g_cluster[clampi(ub.y, 0, N - 1)];
            int s6 = g_cluster[clampi(ub.z, 0, N - 1)];
            int s7 = g_cluster[clampi(ub.w, 0, N - 1)];
            int d0 = g_cluster[clampi(va.x, 0, N - 1)];
            int d1 = g_cluster[clampi(va.y, 0, N - 1)];
            int d2 = g_cluster[clampi(va.z, 0, N - 1)];
            int d3 = g_cluster[clampi(va.w, 0, N - 1)];
            int d4 = g_cluster[clampi(vb.x, 0, N - 1)];
            int d5 = g_cluster[clampi(vb.y, 0, N - 1)];
            int d6 = g_cluster[clampi(vb.z, 0, N - 1)];
            int d7 = g_cluster[clampi(vb.w, 0, N - 1)];
            place32(edge_k32(s0, d0));
            place32(edge_k32(s1, d1));
            place32(edge_k32(s2, d2));
            place32(edge_k32(s3, d3));
            place32(edge_k32(s4, d4));
            place32(edge_k32(s5, d5));
            place32(edge_k32(s6, d6));
            place32(edge_k32(s7, d7));
        } else {
            if (t >= E) return;
            int u = clampi(((const int*)eidx)[t], 0, N - 1);
            int v = clampi(((const int*)eidx)[(size_t)E + t], 0, N - 1);
            place32(edge_k32(g_cluster[u], g_cluster[v]));
        }
    } else {
        if (t >= E) return;
        int u = clampi(ld_id(eidx, t, 1), 0, N - 1);
        int v = clampi(ld_id(eidx, (long long)E + t, 1), 0, N - 1);
        unsigned long long uk = edge_uk64(g_cluster[u], g_cluster[v]);
        if (uk == SENT64) {
            atomicAdd(&g_sent, 1u);
        } else {
            unsigned int b = (unsigned int)(uk >> SH);
            unsigned int pos = atomicAdd(&g_bcnt[b], 1u);
            if (pos < CAP) {
                g_slab[(size_t)b * CAP + pos] = (unsigned short)(uk & LOWMASK);
            } else {
                unsigned int o = atomicAdd(&g_ocnt, 1u);
                if (o < OCAP) g_oflow[o] = uk;
            }
        }
    }
}

// -- shfl-based scans --------------------------------------------------------
__device__ __forceinline__ unsigned int blk_incl_scan_1024(unsigned int v,
                                                           unsigned int* wsum) {
    int t = threadIdx.x;
    #pragma unroll
    for (int d = 1; d < 32; d <<= 1) {
        unsigned int u = __shfl_up_sync(0xFFFFFFFFu, v, d);
        if ((t & 31) >= d) v += u;
    }
    if ((t & 31) == 31) wsum[t >> 5] = v;
    __syncthreads();
    if (t < 32) {
        unsigned int s = wsum[t];
        #pragma unroll
        for (int d = 1; d < 32; d <<= 1) {
            unsigned int u = __shfl_up_sync(0xFFFFFFFFu, s, d);
            if (t >= d) s += u;
        }
        wsum[t] = s;
    }
    __syncthreads();
    if (t >= 32) v += wsum[(t >> 5) - 1];
    return v;
}

__global__ void scan1_kernel() {
    __shared__ unsigned int wsum[32];
    int i = blockIdx.x * 1024 + threadIdx.x;
    unsigned int sb = g_is64 ? SENTB64 : SENTB32;
    unsigned int c = g_bcnt[i] + ((unsigned int)i == sb ? g_sent : 0u);
    unsigned int v = blk_incl_scan_1024(c, wsum);
    g_incl[i] = v;
    if (threadIdx.x == 1023) g_bsum[blockIdx.x] = v;
}
__global__ void scan2_kernel() {
    __shared__ unsigned int wsum[32];
    unsigned int orig = g_bsum[threadIdx.x];
    unsigned int v = blk_incl_scan_1024(orig, wsum);
    g_bsum[threadIdx.x] = v - orig;
}
__global__ void scan3_kernel() {
    int i = blockIdx.x * blockDim.x + threadIdx.x;
    if (i >= NB) return;
    g_incl[i] += g_bsum[i >> 10];
}

// ---------------------------------------------------------------------------
// emit: ONE bucket per warp; warp-uniform validity; incremental decode
// ---------------------------------------------------------------------------
__device__ void emit_run_merged(float* __restrict__ out, int E,
                                unsigned int bucket, long long base,
                                unsigned int n, int is64, int lane,
                                unsigned short* buf, unsigned int* pcnt) {
    const unsigned short* row = g_slab + (size_t)bucket * CAP;
    for (unsigned int i = lane; i < CAP; i += 32) buf[i] = row[i];
    __syncwarp();
    if (lane == 0) {
        unsigned int cnt = CAP;
        unsigned int oc = g_ocnt; if (oc > OCAP) oc = OCAP;
        for (unsigned int i = 0; i < oc && cnt < MBUF; i++) {
            unsigned long long k = g_oflow[i];
            if ((unsigned int)(k >> SH) == bucket)
                buf[cnt++] = (unsigned short)((unsigned int)k & LOWMASK);
        }
        *pcnt = cnt;
    }
    __syncwarp();
    unsigned int cnt = *pcnt;
    if (n > cnt) n = cnt;
    for (unsigned int pass = 0; pass < n; ++pass) {
        unsigned int st = pass & 1u;
        for (unsigned int i = st + 2u * lane; i + 1 < n; i += 64u) {
            unsigned short x0 = buf[i], x1 = buf[i + 1];
            if (x0 > x1) { buf[i] = x1; buf[i + 1] = x0; }
        }
        __syncwarp();
    }
    for (unsigned int i = lane; i < n; i += 32) {
        unsigned int v = buf[i];
        bool first = (i == 0) || (v != (unsigned int)buf[i - 1]);
        emit_pos(out, E, bucket, is64, v, first, base + i);
    }
}

__global__ void bucket_emit_kernel(float* __restrict__ out, int E) {
    __shared__ unsigned short mbuf[8][MBUF];
    __shared__ unsigned int  mcnt[8];
    int wib  = (int)(threadIdx.x >> 5);
    int gw   = (blockIdx.x * blockDim.x + threadIdx.x) >> 5;
    int lane = threadIdx.x & 31;
    unsigned int b = (unsigned int)gw;
    if (b >= NBE) return;
    unsigned int start = (b == 0u) ? 0u : g_incl[b - 1];
    unsigned int n     = g_incl[b] - start;
    if (n == 0u) return;
    int is64 = g_is64;
    unsigned int sentb = is64 ? SENTB64 : SENTB32;

    if (n <= 32u && b != sentb) {
        // fast path: 32-wide register bitonic + incremental decode
        const unsigned short* row = g_slab + (size_t)b * CAP;
        unsigned int v = (lane < (int)n) ? (unsigned int)row[lane] : 0xFFFFFFFFu;
        #pragma unroll
        for (unsigned int k = 2; k <= 32; k <<= 1) {
            for (unsigned int j = k >> 1; j > 0; j >>= 1) {
                unsigned int o = __shfl_xor_sync(0xFFFFFFFFu, v, j);
                bool dirUp = ((lane & k) == 0);
                bool lower = ((lane & j) == 0);
                unsigned int mn = v < o ? v : o, mx = v < o ? o : v;
                v = (lower == dirUp) ? mn : mx;
            }
        }
        unsigned int prev = __shfl_up_sync(0xFFFFFFFFu, v, 1);
        // bucket base decode (warp-uniform)
        int q0; unsigned int r0;
        if (!is64) {
            unsigned int ukb = b << SH;
            unsigned int qb = __umulhi(ukb >> 10, 57266231u);
            unsigned int rb = ukb - qb * 76800u;
            if (rb >= 2048u) { q0 = (int)qb - 27962; r0 = rb - 2048u; }
            else             { q0 = (int)qb - 27963; r0 = rb + 74752u; }
        } else {
            unsigned long long ukb = ((unsigned long long)b) << SH;
            q0 = (int)(ukb / 76800ull);
            r0 = (unsigned int)(ukb - (unsigned long long)q0 * 76800ull);
        }
        bool bvalid = (b < sentb);   // warp-uniform validity
        if (lane < (int)n) {
            bool first = (lane == 0) || (v != prev);
            unsigned int r = r0 + v;
            int carry = (r >= 76800u);
            float sf = (float)(q0 + carry);
            float df = (float)(r - (carry ? 76800u : 0u));
            bool mask = first && bvalid;
            const long long off_ei = OFF_EI;
            const long long off_em = off_ei + 2ll * E;
            long long p = (long long)(start + (unsigned int)lane);
            out[off_ei + p]     = mask ? sf   : -1.0f;
            out[off_ei + E + p] = mask ? df   : -1.0f;
            out[off_em + p]     = mask ? 1.0f : 0.0f;
        }
    } else {
        // rare path: sentinel bucket and/or n > 32
        long long base = (long long)start;
        unsigned int nn = n;
        if (b == sentb) {
            unsigned int S = g_sent;
            if (S > n) S = n;
            const long long off_ei = OFF_EI;
            const long long off_em = off_ei + 2ll * E;
            for (unsigned int i = lane; i < S; i += 32) {
                long long p = base + i;
                out[off_ei + p]     = -1.0f;
                out[off_ei + E + p] = -1.0f;
                out[off_em + p]     = 0.0f;
            }
            base += S; nn = n - S;
            if (nn == 0) return;
        }
        if (nn <= 32u) {
            const unsigned short* row = g_slab + (size_t)b * CAP;
            unsigned int v = (lane < (int)nn) ? (unsigned int)row[lane] : 0xFFFFFFFFu;
            #pragma unroll
            for (unsigned int k = 2; k <= 32; k <<= 1) {
                for (unsigned int j = k >> 1; j > 0; j >>= 1) {
                    unsigned int o = __shfl_xor_sync(0xFFFFFFFFu, v, j);
                    bool dirUp = ((lane & k) == 0);
                    bool lower = ((lane & j) == 0);
                    unsigned int mn = v < o ? v : o, mx = v < o ? o : v;
                    v = (lower == dirUp) ? mn : mx;
                }
            }
            unsigned int prev = __shfl_up_sync(0xFFFFFFFFu, v, 1);
            if (lane < (int)nn) {
                bool first = (lane == 0) || (v != prev);
                emit_pos(out, E, b, is64, v, first, base + lane);
            }
        } else {
            emit_run_merged(out, E, b, base, nn, is64, lane, mbuf[wib], &mcnt[wib]);
        }
    }
}

// ---------------------------------------------------------------------------
// Launch: fork-join — edge chain (main) || node chain (side)
// ---------------------------------------------------------------------------
extern "C" void kernel_launch(void* const* d_in, const int* in_sizes, int n_in,
                              void* d_out, int out_size) {
    int ib = 0;
    for (int i = 1; i < n_in && i < 4; i++)
        if (in_sizes[i] < in_sizes[ib]) ib = i;
    long long N = in_sizes[ib];
    int ix = -1, ip = -1, ie = -1;
    for (int i = 0; i < n_in && i < 4; i++) {
        if (i == ib) continue;
        long long s = in_sizes[i];
        if (s == 64 * N)     ix = i;
        else if (s == 3 * N) ip = i;
        else                 ie = i;
    }
    if (ix < 0 || ip < 0 || ie < 0) { ix = 0; ip = 1; ib = 2; ie = 3; }

    const float* x    = (const float*)d_in[ix];
    const float* pos  = (const float*)d_in[ip];
    const void*  bat  = d_in[ib];
    const void*  eidx = d_in[ie];
    float*       out  = (float*)d_out;

    int Ni = (int)N;
    int E  = in_sizes[ie] / 2;
    if (Ni > N_MAX) Ni = N_MAX;
    if (E > E_MAX)  E  = E_MAX;

    static cudaStream_t s1 = nullptr;
    static cudaEvent_t evFork = nullptr, evJoin = nullptr;
    if (!s1) {
        cudaStreamCreateWithFlags(&s1, cudaStreamNonBlocking);
        cudaEventCreateWithFlags(&evFork, cudaEventDisableTiming);
        cudaEventCreateWithFlags(&evJoin, cudaEventDisableTiming);
    }

    const int T = 256;
    init_kernel<<<(NB / 4 + T - 1) / T, T>>>((const unsigned int*)eidx);        // 1
    cluster_kernel<<<(Ni + T - 1) / T, T>>>(pos, bat, Ni);                       // 2

    // fork: side stream runs the node chain
    cudaEventRecord(evFork, 0);
    cudaStreamWaitEvent(s1, evFork, 0);
    nodescan_kernel<<<1, 1024, 0, s1>>>();                                       // 3

    // main: fused edge pass (8 edges/thread in i32 mode)
    {
        int thr = ((E & 7) == 0) ? (E >> 3) : E;   // i32 fast path; is64 uses E
        if (thr < E) thr = E;                      // cover is64 path too
        edge_fused_kernel<<<(thr + T - 1) / T, T>>>(eidx, Ni, E);                // 4
    }

    nodescatter_kernel<<<(Ni + T - 1) / T, T, 0, s1>>>(Ni);                      // 5
    xmax2_kernel<<<(KC * 32 + T - 1) / T, T, 0, s1>>>(x, out, Ni);               // 6
    finalize_kernel<<<(KC * 3 + T - 1) / T, T, 0, s1>>>(out);                    // 7
    cudaEventRecord(evJoin, s1);

    scan1_kernel<<<NBLK, 1024>>>();                                              // 8
    scan2_kernel<<<1, 1024>>>();                                                 // 9
    scan3_kernel<<<NB / 1024, 1024>>>();                                         // 10
    bucket_emit_kernel<<<(NBE * 32 + T - 1) / T, T>>>(out, E);                   // 11

    cudaStreamWaitEvent(0, evJoin, 0);
    (void)out_size;
}